// round 11
// baseline (speedup 1.0000x reference)
#include <cuda_runtime.h>
#include <cuda_bf16.h>
#include <cstdint>
#include <math.h>

#define C_CLASSES 1024
#define ALLNUM    8192
#define DIMK      512
#define TOPK      410
#define BATCH     2048
#define LAMB      0.3f

// ---------------- scratch (static device globals: no allocation) ----------------
__device__ float g_invnorm[ALLNUM];
__device__ float g_norm2p[8][ALLNUM];                      // partial column norms
__device__ float g_sim[(size_t)BATCH * ALLNUM];            // 64 MB
__device__ float g_CL[(size_t)ALLNUM * C_CLASSES];         // 32 MB
__device__ float g_lossb[BATCH];
__device__ float g_regb[ALLNUM];
__device__ int   g_is64;
__device__ int   g_il_seq;

// bf16 hi/lo split operands, all row-major [row][512]
__device__ __nv_bfloat16 gAh[(size_t)BATCH * DIMK];        // input
__device__ __nv_bfloat16 gAl[(size_t)BATCH * DIMK];
__device__ __nv_bfloat16 gCTh[(size_t)ALLNUM * DIMK];      // centers^T (scaled)
__device__ __nv_bfloat16 gCTl[(size_t)ALLNUM * DIMK];
__device__ __nv_bfloat16 gGTh[(size_t)C_CLASSES * DIMK];   // G^T (class sums)
__device__ __nv_bfloat16 gGTl[(size_t)C_CLASSES * DIMK];

// ---------------- helpers ----------------
__device__ __forceinline__ long long load_idx(const void* p, int i) {
    if (g_is64) return ((const long long*)p)[i];
    return (long long)((const int*)p)[i];
}
__device__ __forceinline__ uint32_t sptr(const void* p) {
    return (uint32_t)__cvta_generic_to_shared(p);
}
__device__ __forceinline__ void cpa16(uint32_t saddr, const void* g) {
    asm volatile("cp.async.cg.shared.global [%0], [%1], 16;" :: "r"(saddr), "l"(g));
}
#define CPA_COMMIT() asm volatile("cp.async.commit_group;" ::: "memory")
#define CPA_WAIT(n)  asm volatile("cp.async.wait_group %0;" :: "n"(n) : "memory")

__device__ __forceinline__ void ldsm_x4(uint32_t r[4], uint32_t addr) {
    asm volatile("ldmatrix.sync.aligned.m8n8.x4.shared.b16 {%0,%1,%2,%3}, [%4];"
                 : "=r"(r[0]), "=r"(r[1]), "=r"(r[2]), "=r"(r[3]) : "r"(addr));
}
__device__ __forceinline__ void mma_bf16(float d[4], const uint32_t a[4],
                                         const uint32_t b[2]) {
    asm volatile(
        "mma.sync.aligned.m16n8k16.row.col.f32.bf16.bf16.f32 "
        "{%0,%1,%2,%3}, {%4,%5,%6,%7}, {%8,%9}, {%0,%1,%2,%3};"
        : "+f"(d[0]), "+f"(d[1]), "+f"(d[2]), "+f"(d[3])
        : "r"(a[0]), "r"(a[1]), "r"(a[2]), "r"(a[3]), "r"(b[0]), "r"(b[1]));
}

// ---------------- 1: partial column norms + (block 0) index detection ----------------
__global__ void k_norm2(const float* __restrict__ P, const unsigned int* __restrict__ t,
                        const void* __restrict__ il) {
    int a = blockIdx.x * 256 + threadIdx.x;
    int d0 = blockIdx.y * 64;
    float s0 = 0.f, s1 = 0.f, s2 = 0.f, s3 = 0.f;
#pragma unroll 4
    for (int d = 0; d < 64; d += 4) {
        float v0 = P[(size_t)(d0 + d + 0) * ALLNUM + a];
        float v1 = P[(size_t)(d0 + d + 1) * ALLNUM + a];
        float v2 = P[(size_t)(d0 + d + 2) * ALLNUM + a];
        float v3 = P[(size_t)(d0 + d + 3) * ALLNUM + a];
        s0 = fmaf(v0, v0, s0); s1 = fmaf(v1, v1, s1);
        s2 = fmaf(v2, v2, s2); s3 = fmaf(v3, v3, s3);
    }
    g_norm2p[blockIdx.y][a] = (s0 + s1) + (s2 + s3);

    // block (0,0): detect int64 vs int32, and whether il == repeat(arange(1024),8)
    if (blockIdx.x == 0 && blockIdx.y == 0) {
        __shared__ int s64, sok;
        if (threadIdx.x == 0) {
            int is64 = 1;
            for (int k = 0; k < 8; k++)
                if (t[2 * k + 1] != 0u) is64 = 0;
            g_is64 = is64; s64 = is64; sok = 1;
        }
        __syncthreads();
        int ok = 1;
        for (int i = threadIdx.x; i < ALLNUM; i += 256) {
            long long v = s64 ? ((const long long*)il)[i] : (long long)((const int*)il)[i];
            if (v != (long long)(i >> 3)) ok = 0;
        }
        if (!ok) atomicAnd(&sok, 0);
        __syncthreads();
        if (threadIdx.x == 0) g_il_seq = sok;
    }
}

// ---------------- 2: finalize inverse norms ----------------
__global__ void k_fin_norm() {
    int a = blockIdx.x * 256 + threadIdx.x;
    float s = 0.f;
#pragma unroll
    for (int j = 0; j < 8; j++) s += g_norm2p[j][a];
    g_invnorm[a] = 1.0f / fmaxf(sqrtf(s), 1e-12f);
}

// ---------------- 3: split input A -> bf16 hi/lo ----------------
__global__ void k_split_A(const float* __restrict__ A) {
    int i = blockIdx.x * 256 + threadIdx.x;
    float x = A[i];
    __nv_bfloat16 h = __float2bfloat16(x);
    gAh[i] = h;
    gAl[i] = __float2bfloat16(x - __bfloat162float(h));
}

// ---------------- 4: class-summed centers -> split G^T[c][d] ----------------
__global__ void k_groupsum(const float* __restrict__ P, const void* __restrict__ il) {
    int d = blockIdx.x;                               // 512 blocks
    int tid = threadIdx.x;
    const float* Pd = P + (size_t)d * ALLNUM;
    if (g_il_seq) {
        // il[a] = a>>3: direct 8-wide sums, no atomics, deterministic
        for (int c = tid; c < C_CLASSES; c += 256) {
            const float4* p = (const float4*)(Pd + 8 * c);
            const float4* iv = (const float4*)(g_invnorm + 8 * c);
            float4 a0 = p[0], a1 = p[1], i0 = iv[0], i1 = iv[1];
            float s = a0.x * i0.x + a0.y * i0.y + a0.z * i0.z + a0.w * i0.w +
                      a1.x * i1.x + a1.y * i1.y + a1.z * i1.z + a1.w * i1.w;
            __nv_bfloat16 h = __float2bfloat16(s);
            gGTh[(size_t)c * DIMK + d] = h;
            gGTl[(size_t)c * DIMK + d] = __float2bfloat16(s - __bfloat162float(h));
        }
    } else {
        __shared__ float g[C_CLASSES];
        for (int c = tid; c < C_CLASSES; c += 256) g[c] = 0.f;
        __syncthreads();
        for (int a = tid; a < ALLNUM; a += 256)
            atomicAdd(&g[(int)load_idx(il, a)], Pd[a] * g_invnorm[a]);
        __syncthreads();
        for (int c = tid; c < C_CLASSES; c += 256) {
            float s = g[c];
            __nv_bfloat16 h = __float2bfloat16(s);
            gGTh[(size_t)c * DIMK + d] = h;
            gGTl[(size_t)c * DIMK + d] = __float2bfloat16(s - __bfloat162float(h));
        }
    }
}

// ---------------- 5: split scaled centers -> transposed bf16 [a][k] ----------------
__global__ __launch_bounds__(256) void k_split_PT(const float* __restrict__ P) {
    __shared__ __nv_bfloat16 sh[64 * 66], sl[64 * 66];
    int ab = blockIdx.x * 64, kb = blockIdx.y * 64;
    int tid = threadIdx.x;
#pragma unroll
    for (int r = 0; r < 16; r++) {
        int idx = tid + r * 256;
        int kr = idx >> 6, ac = idx & 63;
        float v = P[(size_t)(kb + kr) * ALLNUM + ab + ac] * g_invnorm[ab + ac];
        __nv_bfloat16 h = __float2bfloat16(v);
        sh[kr * 66 + ac] = h;
        sl[kr * 66 + ac] = __float2bfloat16(v - __bfloat162float(h));
    }
    __syncthreads();
#pragma unroll
    for (int r = 0; r < 16; r++) {
        int idx = tid + r * 256;
        int ar = idx >> 6, kc = idx & 63;
        size_t go = (size_t)(ab + ar) * DIMK + kb + kc;
        gCTh[go] = sh[kc * 66 + ar];
        gCTl[go] = sl[kc * 66 + ar];
    }
}

// ---------------- 6: fused bf16-split tensor-core GEMMs ----------------
// Both operands row-major [row][512]. C[m][n] = sum_k A[m][k]*B[n][k].
// 3 passes (AhBh + AhBl + AlBh), fp32 acc. CTA 128x128, 8 warps, warp 64x32,
// K chunk 32, 2-stage cp.async pipeline. B fed with NON-trans ldsm (B^T rows).
// grid: blocks [0,1024) -> GEMM1 (sim), [1024,1536) -> GEMM2 (CL).
// smem: matrix m in {Ah,Al,Bh,Bl}, stage s: offset (m*2+s)*5120 bf16 elems.
#define MMA_SMEM (8 * 5120 * 2)    // 81920 B
__global__ __launch_bounds__(256, 2) void k_mma(
    const __nv_bfloat16* __restrict__ pAh, const __nv_bfloat16* __restrict__ pAl,
    const __nv_bfloat16* __restrict__ pCTh, const __nv_bfloat16* __restrict__ pCTl,
    const __nv_bfloat16* __restrict__ pGTh, const __nv_bfloat16* __restrict__ pGTl,
    float* __restrict__ pSim, float* __restrict__ pCL) {
    extern __shared__ __align__(16) __nv_bfloat16 smem[];

    const __nv_bfloat16 *Ah, *Al, *Bh, *Bl;
    float* Out;
    int N, bm, bn;
    int cta = blockIdx.x;
    if (cta < 1024) {
        bm = (cta >> 6) * 128; bn = (cta & 63) * 128;
        Ah = pAh; Al = pAl; Bh = pCTh; Bl = pCTl; Out = pSim; N = ALLNUM;
    } else {
        int t = cta - 1024;
        bm = (t >> 3) * 128; bn = (t & 7) * 128;
        Ah = pCTh; Al = pCTl; Bh = pGTh; Bl = pGTl; Out = pCL; N = C_CLASSES;
    }

    int tid = threadIdx.x;
    int lane = tid & 31, w = tid >> 5;
    int wm = (w & 1) * 64, wn = (w >> 1) * 32;

    float acc[4][4][4];
#pragma unroll
    for (int i = 0; i < 4; i++)
#pragma unroll
        for (int j = 0; j < 4; j++)
#pragma unroll
            for (int q = 0; q < 4; q++) acc[i][j][q] = 0.f;

#define LOAD_STAGE(k0, s)                                                        \
    do {                                                                         \
        __nv_bfloat16* dAh = smem + (0 * 2 + (s)) * 5120;                        \
        __nv_bfloat16* dAl = smem + (1 * 2 + (s)) * 5120;                        \
        __nv_bfloat16* dBh = smem + (2 * 2 + (s)) * 5120;                        \
        __nv_bfloat16* dBl = smem + (3 * 2 + (s)) * 5120;                        \
        _Pragma("unroll")                                                        \
        for (int r = 0; r < 2; r++) {                                            \
            int idx = tid + r * 256;                                             \
            int row = idx >> 2, c4 = (idx & 3) * 8;                              \
            size_t ga = (size_t)(bm + row) * DIMK + (k0) + c4;                   \
            size_t gb = (size_t)(bn + row) * DIMK + (k0) + c4;                   \
            cpa16(sptr(dAh + row * 40 + c4), Ah + ga);                           \
            cpa16(sptr(dAl + row * 40 + c4), Al + ga);                           \
            cpa16(sptr(dBh + row * 40 + c4), Bh + gb);                           \
            cpa16(sptr(dBl + row * 40 + c4), Bl + gb);                           \
        }                                                                        \
    } while (0)

    LOAD_STAGE(0, 0);
    CPA_COMMIT();

    for (int c = 0; c < 16; c++) {
        int s = c & 1;
        if (c + 1 < 16) {
            LOAD_STAGE((c + 1) * 32, s ^ 1);
            CPA_COMMIT();
            CPA_WAIT(1);
        } else {
            CPA_WAIT(0);
        }
        __syncthreads();

        const __nv_bfloat16* sAh = smem + (0 * 2 + s) * 5120;
        const __nv_bfloat16* sAl = smem + (1 * 2 + s) * 5120;
        const __nv_bfloat16* sBh = smem + (2 * 2 + s) * 5120;
        const __nv_bfloat16* sBl = smem + (3 * 2 + s) * 5120;
#pragma unroll
        for (int kf = 0; kf < 32; kf += 16) {
            uint32_t ah[4][4], al[4][4], bh[4][2], bl[4][2], t[4];
            int aoff = (wm + (lane & 15)) * 40 + kf + (lane >> 4) * 8;
#pragma unroll
            for (int mt = 0; mt < 4; mt++) {
                ldsm_x4(ah[mt], sptr(sAh + aoff + mt * 16 * 40));
                ldsm_x4(al[mt], sptr(sAl + aoff + mt * 16 * 40));
            }
            int boff = (wn + (lane & 15)) * 40 + kf + (lane >> 4) * 8;
#pragma unroll
            for (int j = 0; j < 2; j++) {
                // non-trans ldsm on B^T rows: r0=(n0-8,k0-8) r1=(n8-16,k0-8)
                //                             r2=(n0-8,k8-16) r3=(n8-16,k8-16)
                ldsm_x4(t, sptr(sBh + boff + j * 16 * 40));
                bh[2 * j][0] = t[0]; bh[2 * j][1] = t[2];
                bh[2 * j + 1][0] = t[1]; bh[2 * j + 1][1] = t[3];
                ldsm_x4(t, sptr(sBl + boff + j * 16 * 40));
                bl[2 * j][0] = t[0]; bl[2 * j][1] = t[2];
                bl[2 * j + 1][0] = t[1]; bl[2 * j + 1][1] = t[3];
            }
#pragma unroll
            for (int mt = 0; mt < 4; mt++)
#pragma unroll
                for (int nt = 0; nt < 4; nt++) {
                    mma_bf16(acc[mt][nt], ah[mt], bh[nt]);
                    mma_bf16(acc[mt][nt], ah[mt], bl[nt]);
                    mma_bf16(acc[mt][nt], al[mt], bh[nt]);
                }
        }
        __syncthreads();
    }

    int g = lane >> 2, t4 = (lane & 3) * 2;
#pragma unroll
    for (int mt = 0; mt < 4; mt++)
#pragma unroll
        for (int nt = 0; nt < 4; nt++) {
            int r0 = bm + wm + mt * 16 + g;
            int cc = bn + wn + nt * 8 + t4;
            *(float2*)&Out[(size_t)r0 * N + cc] =
                make_float2(acc[mt][nt][0], acc[mt][nt][1]);
            *(float2*)&Out[(size_t)(r0 + 8) * N + cc] =
                make_float2(acc[mt][nt][2], acc[mt][nt][3]);
        }
#undef LOAD_STAGE
}

// ---------------- 7: per-row top-k threshold + masked-softmax classify loss ----------------
__global__ __launch_bounds__(256) void k_classify(const void* __restrict__ target,
                                                  const void* __restrict__ il) {
    __shared__ unsigned int uvals[ALLNUM];   // 32 KB
    __shared__ unsigned int hist[256];
    __shared__ float slog[C_CLASSES];        // 4 KB
    __shared__ float red[256];
    __shared__ unsigned int sh_prefix;
    __shared__ int sh_k;

    int tid = threadIdx.x;
    int lane = tid & 31;
    int b = blockIdx.x;
    int seq = g_il_seq;
    long long tgt = load_idx(target, b);
    const float* Srow = g_sim + (size_t)b * ALLNUM;

    if (seq) {
        for (int i = tid; i < ALLNUM; i += 256) {
            unsigned int bits = __float_as_uint(Srow[i]);
            uvals[i] = (bits & 0x80000000u) ? ~bits : (bits | 0x80000000u);
        }
    } else {
        for (int i = tid; i < ALLNUM; i += 256) {
            float v = Srow[i] + ((load_idx(il, i) == tgt) ? 1000.0f : 0.0f);
            unsigned int bits = __float_as_uint(v);
            uvals[i] = (bits & 0x80000000u) ? ~bits : (bits | 0x80000000u);
        }
    }
    for (int c = tid; c < C_CLASSES; c += 256) slog[c] = 0.f;
    if (tid == 0) { sh_prefix = 0u; sh_k = TOPK; }
    __syncthreads();
    if (seq && tid < 8) {           // patch the 8 boosted (target-class) entries
        int i = ((int)tgt << 3) + tid;
        unsigned int bits = __float_as_uint(Srow[i] + 1000.0f);
        uvals[i] = (bits & 0x80000000u) ? ~bits : (bits | 0x80000000u);
    }

    for (int shift = 24; shift >= 0; shift -= 8) {
        hist[tid] = 0u;
        __syncthreads();
        unsigned int pfx = sh_prefix;
        int k = sh_k;
        unsigned int hm = (shift == 24) ? 0u : (0xFFFFFFFFu << (shift + 8));
        for (int i = tid; i < ALLNUM; i += 256) {
            unsigned int u = uvals[i];
            int bin = ((u & hm) == pfx) ? (int)((u >> shift) & 255u) : -1;
            unsigned int m = __match_any_sync(0xffffffffu, bin);
            if (bin >= 0 && lane == (int)(__ffs(m) - 1))
                atomicAdd(&hist[bin], (unsigned int)__popc(m));
        }
        __syncthreads();
        if (tid == 0) {
            int cum = 0, d = 255;
            for (; d >= 0; d--) { cum += (int)hist[d]; if (cum >= k) break; }
            sh_k = k - (cum - (int)hist[d]);
            sh_prefix = pfx | ((unsigned int)d << shift);
        }
        __syncthreads();
    }
    unsigned int tau = sh_prefix;

    if (seq) {
        for (int i = tid; i < ALLNUM; i += 256) {
            if (uvals[i] >= tau) atomicAdd(&slog[i >> 3], Srow[i]);
        }
    } else {
        for (int i = tid; i < ALLNUM; i += 256) {
            if (uvals[i] >= tau) atomicAdd(&slog[(int)load_idx(il, i)], Srow[i]);
        }
    }
    __syncthreads();

    float part = 0.f;
    for (int c = tid; c < C_CLASSES; c += 256) {
        float l = slog[c];
        part += (l == 0.0f) ? 0.0f : expf(l);
    }
    red[tid] = part;
    __syncthreads();
    for (int st = 128; st; st >>= 1) {
        if (tid < st) red[tid] += red[tid + st];
        __syncthreads();
    }
    if (tid == 0) {
        float S = red[0];
        float lt = slog[(int)tgt];
        float et = (lt == 0.0f) ? 0.0f : expf(lt);
        float predict = et / (1e-8f + S);
        g_lossb[b] = -logf(predict + 1e-20f);
    }
}

// ---------------- 8: proxy regularizer: per-row logsumexp over classes ----------------
__global__ void k_reg(const void* __restrict__ il) {
    int warp = threadIdx.x >> 5, lane = threadIdx.x & 31;
    int row = blockIdx.x * 8 + warp;
    const float* r = g_CL + (size_t)row * C_CLASSES;
    float mx = -3.4e38f;
    for (int c = lane; c < C_CLASSES; c += 32) mx = fmaxf(mx, r[c]);
    for (int o = 16; o; o >>= 1) mx = fmaxf(mx, __shfl_xor_sync(0xffffffffu, mx, o));
    float s = 0.f;
    for (int c = lane; c < C_CLASSES; c += 32) s += expf(r[c] - mx);
    for (int o = 16; o; o >>= 1) s += __shfl_xor_sync(0xffffffffu, s, o);
    if (lane == 0) {
        int cls = g_il_seq ? (row >> 3) : (int)load_idx(il, row);
        g_regb[row] = (mx + logf(s)) - r[cls];
    }
}

// ---------------- 9: deterministic final reduction ----------------
__global__ void k_final(float* __restrict__ out, int out_size) {
    __shared__ float red[256];
    int tid = threadIdx.x;
    float s = 0.f;
    for (int i = tid; i < BATCH; i += 256) s += g_lossb[i];
    red[tid] = s;
    __syncthreads();
    for (int st = 128; st; st >>= 1) {
        if (tid < st) red[tid] += red[tid + st];
        __syncthreads();
    }
    float lc = red[0] / (float)BATCH;
    __syncthreads();
    s = 0.f;
    for (int i = tid; i < ALLNUM; i += 256) s += g_regb[i];
    red[tid] = s;
    __syncthreads();
    for (int st = 128; st; st >>= 1) {
        if (tid < st) red[tid] += red[tid + st];
        __syncthreads();
    }
    if (tid == 0) {
        float reg = red[0] / (float)ALLNUM;
        out[0] = lc + LAMB * reg;
        if (out_size > 1) out[1] = lc;
    }
}

// ---------------- launch ----------------
extern "C" void kernel_launch(void* const* d_in, const int* in_sizes, int n_in,
                              void* d_out, int out_size) {
    const float* input   = (const float*)d_in[0];
    const void*  target  = d_in[1];
    const float* proxies = (const float*)d_in[2];
    const void*  il      = d_in[3];
    float* out = (float*)d_out;

    static __nv_bfloat16 *pAh, *pAl, *pCTh, *pCTl, *pGTh, *pGTl;
    static float *pSim, *pCL;
    static bool init = false;
    if (!init) {
        cudaGetSymbolAddress((void**)&pAh, gAh);
        cudaGetSymbolAddress((void**)&pAl, gAl);
        cudaGetSymbolAddress((void**)&pCTh, gCTh);
        cudaGetSymbolAddress((void**)&pCTl, gCTl);
        cudaGetSymbolAddress((void**)&pGTh, gGTh);
        cudaGetSymbolAddress((void**)&pGTl, gGTl);
        cudaGetSymbolAddress((void**)&pSim, g_sim);
        cudaGetSymbolAddress((void**)&pCL, g_CL);
        cudaFuncSetAttribute(k_mma, cudaFuncAttributeMaxDynamicSharedMemorySize,
                             MMA_SMEM);
        init = true;
    }

    // launches 1-5 (prologue), so ncu -s 5 -c 1 captures the fused k_mma (#6)
    dim3 gn(ALLNUM / 256, 8);
    k_norm2<<<gn, 256>>>(proxies, (const unsigned int*)target, il);   // #1
    k_fin_norm<<<ALLNUM / 256, 256>>>();                              // #2
    k_split_A<<<(BATCH * DIMK) / 256, 256>>>(input);                  // #3
    k_groupsum<<<DIMK, 256>>>(proxies, il);                           // #4
    dim3 gpt(ALLNUM / 64, DIMK / 64);
    k_split_PT<<<gpt, 256>>>(proxies);                                // #5

    // #6: fused GEMM1 (1024 CTAs) + GEMM2 (512 CTAs)
    k_mma<<<1536, 256, MMA_SMEM>>>(pAh, pAl, pCTh, pCTl, pGTh, pGTl, pSim, pCL);

    k_classify<<<BATCH, 256>>>(target, il);                           // #7
    k_reg<<<ALLNUM / 8, 256>>>(il);                                   // #8
    k_final<<<1, 256>>>(out, out_size);                               // #9
}

// round 12
// speedup vs baseline: 1.0272x; 1.0272x over previous
#include <cuda_runtime.h>
#include <cuda_bf16.h>
#include <cstdint>
#include <math.h>

#define C_CLASSES 1024
#define ALLNUM    8192
#define DIMK      512
#define TOPK      410
#define BATCH     2048
#define LAMB      0.3f

// ---------------- scratch (static device globals: no allocation) ----------------
__device__ float g_invnorm[ALLNUM];
__device__ float g_norm2p[8][ALLNUM];
__device__ float g_sim[(size_t)BATCH * ALLNUM];            // 64 MB
__device__ float g_sumexp[ALLNUM];                         // reg: per-proxy sum of exp(CL)
__device__ float g_diag[ALLNUM];                           // reg: CL[a][a>>3]
__device__ float g_lossb[BATCH];
__device__ float g_regb[ALLNUM];
__device__ int   g_is64;
__device__ int   g_il_seq;

// bf16 hi/lo split operands, all row-major [row][512]
__device__ __nv_bfloat16 gAh[(size_t)BATCH * DIMK];        // input
__device__ __nv_bfloat16 gAl[(size_t)BATCH * DIMK];
__device__ __nv_bfloat16 gCTh[(size_t)ALLNUM * DIMK];      // centers^T (scaled)
__device__ __nv_bfloat16 gCTl[(size_t)ALLNUM * DIMK];
__device__ __nv_bfloat16 gGTh[(size_t)C_CLASSES * DIMK];   // G^T (class sums)
__device__ __nv_bfloat16 gGTl[(size_t)C_CLASSES * DIMK];

// ---------------- helpers ----------------
__device__ __forceinline__ long long load_idx(const void* p, int i) {
    if (g_is64) return ((const long long*)p)[i];
    return (long long)((const int*)p)[i];
}
__device__ __forceinline__ uint32_t sptr(const void* p) {
    return (uint32_t)__cvta_generic_to_shared(p);
}
__device__ __forceinline__ void cpa16(uint32_t saddr, const void* g) {
    asm volatile("cp.async.cg.shared.global [%0], [%1], 16;" :: "r"(saddr), "l"(g));
}
#define CPA_COMMIT() asm volatile("cp.async.commit_group;" ::: "memory")
#define CPA_WAIT(n)  asm volatile("cp.async.wait_group %0;" :: "n"(n) : "memory")

__device__ __forceinline__ void ldsm_x4(uint32_t r[4], uint32_t addr) {
    asm volatile("ldmatrix.sync.aligned.m8n8.x4.shared.b16 {%0,%1,%2,%3}, [%4];"
                 : "=r"(r[0]), "=r"(r[1]), "=r"(r[2]), "=r"(r[3]) : "r"(addr));
}
__device__ __forceinline__ void mma_bf16(float d[4], const uint32_t a[4],
                                         const uint32_t b[2]) {
    asm volatile(
        "mma.sync.aligned.m16n8k16.row.col.f32.bf16.bf16.f32 "
        "{%0,%1,%2,%3}, {%4,%5,%6,%7}, {%8,%9}, {%0,%1,%2,%3};"
        : "+f"(d[0]), "+f"(d[1]), "+f"(d[2]), "+f"(d[3])
        : "r"(a[0]), "r"(a[1]), "r"(a[2]), "r"(a[3]), "r"(b[0]), "r"(b[1]));
}

// ---------------- 1: partial column norms + index/label-pattern detection ----------------
__global__ void k_norm2(const float* __restrict__ P, const unsigned int* __restrict__ t,
                        const void* __restrict__ il) {
    int a = blockIdx.x * 256 + threadIdx.x;
    int d0 = blockIdx.y * 64;
    float s0 = 0.f, s1 = 0.f, s2 = 0.f, s3 = 0.f;
#pragma unroll 4
    for (int d = 0; d < 64; d += 4) {
        float v0 = P[(size_t)(d0 + d + 0) * ALLNUM + a];
        float v1 = P[(size_t)(d0 + d + 1) * ALLNUM + a];
        float v2 = P[(size_t)(d0 + d + 2) * ALLNUM + a];
        float v3 = P[(size_t)(d0 + d + 3) * ALLNUM + a];
        s0 = fmaf(v0, v0, s0); s1 = fmaf(v1, v1, s1);
        s2 = fmaf(v2, v2, s2); s3 = fmaf(v3, v3, s3);
    }
    g_norm2p[blockIdx.y][a] = (s0 + s1) + (s2 + s3);

    if (blockIdx.x == 0 && blockIdx.y == 0) {
        __shared__ int s64, sok;
        if (threadIdx.x == 0) {
            int is64 = 1;
            for (int k = 0; k < 8; k++)
                if (t[2 * k + 1] != 0u) is64 = 0;
            g_is64 = is64; s64 = is64; sok = 1;
        }
        __syncthreads();
        int ok = 1;
        for (int i = threadIdx.x; i < ALLNUM; i += 256) {
            long long v = s64 ? ((const long long*)il)[i] : (long long)((const int*)il)[i];
            if (v != (long long)(i >> 3)) ok = 0;
        }
        if (!ok) atomicAnd(&sok, 0);
        __syncthreads();
        if (threadIdx.x == 0) g_il_seq = sok;
    }
}

// ---------------- 2: finalize inverse norms ----------------
__global__ void k_fin_norm() {
    int a = blockIdx.x * 256 + threadIdx.x;
    float s = 0.f;
#pragma unroll
    for (int j = 0; j < 8; j++) s += g_norm2p[j][a];
    g_invnorm[a] = 1.0f / fmaxf(sqrtf(s), 1e-12f);
}

// ---------------- 3: fused prep: split_A | groupsum->G^T | split_PT | zero sums ----------
// flat grid: [0,4096) split_A, [4096,4608) groupsum, [4608,5632) split_PT, [5632,5664) zero
__global__ __launch_bounds__(256) void k_prep(const float* __restrict__ A,
                                              const float* __restrict__ P,
                                              const void* __restrict__ il) {
    int b = blockIdx.x, tid = threadIdx.x;
    if (b < 4096) {
        int i = b * 256 + tid;
        float x = A[i];
        __nv_bfloat16 h = __float2bfloat16(x);
        gAh[i] = h;
        gAl[i] = __float2bfloat16(x - __bfloat162float(h));
    } else if (b < 4608) {
        int d = b - 4096;
        const float* Pd = P + (size_t)d * ALLNUM;
        if (g_il_seq) {
            for (int c = tid; c < C_CLASSES; c += 256) {
                const float4* p = (const float4*)(Pd + 8 * c);
                const float4* iv = (const float4*)(g_invnorm + 8 * c);
                float4 a0 = p[0], a1 = p[1], i0 = iv[0], i1 = iv[1];
                float s = a0.x * i0.x + a0.y * i0.y + a0.z * i0.z + a0.w * i0.w +
                          a1.x * i1.x + a1.y * i1.y + a1.z * i1.z + a1.w * i1.w;
                __nv_bfloat16 h = __float2bfloat16(s);
                gGTh[(size_t)c * DIMK + d] = h;
                gGTl[(size_t)c * DIMK + d] = __float2bfloat16(s - __bfloat162float(h));
            }
        } else {
            __shared__ float g[C_CLASSES];
            for (int c = tid; c < C_CLASSES; c += 256) g[c] = 0.f;
            __syncthreads();
            for (int a = tid; a < ALLNUM; a += 256)
                atomicAdd(&g[(int)load_idx(il, a)], Pd[a] * g_invnorm[a]);
            __syncthreads();
            for (int c = tid; c < C_CLASSES; c += 256) {
                float s = g[c];
                __nv_bfloat16 h = __float2bfloat16(s);
                gGTh[(size_t)c * DIMK + d] = h;
                gGTl[(size_t)c * DIMK + d] = __float2bfloat16(s - __bfloat162float(h));
            }
        }
    } else if (b < 5632) {
        __shared__ __nv_bfloat16 sh[64 * 66], sl[64 * 66];
        int t = b - 4608;
        int ab = (t & 127) * 64, kb = (t >> 7) * 64;
#pragma unroll
        for (int r = 0; r < 16; r++) {
            int idx = tid + r * 256;
            int kr = idx >> 6, ac = idx & 63;
            float v = P[(size_t)(kb + kr) * ALLNUM + ab + ac] * g_invnorm[ab + ac];
            __nv_bfloat16 h = __float2bfloat16(v);
            sh[kr * 66 + ac] = h;
            sl[kr * 66 + ac] = __float2bfloat16(v - __bfloat162float(h));
        }
        __syncthreads();
#pragma unroll
        for (int r = 0; r < 16; r++) {
            int idx = tid + r * 256;
            int ar = idx >> 6, kc = idx & 63;
            size_t go = (size_t)(ab + ar) * DIMK + kb + kc;
            gCTh[go] = sh[kc * 66 + ar];
            gCTl[go] = sl[kc * 66 + ar];
        }
    } else {
        int i = (b - 5632) * 256 + tid;   // zero reg accumulators (graph replays!)
        g_sumexp[i] = 0.f;
    }
}

// ---------------- 4: fused bf16-split tensor-core GEMMs + reg-exp epilogue ----------------
// Both operands row-major [row][512]. C[m][n] = sum_k A[m][k]*B[n][k].
// 3 passes (AhBh + AhBl + AlBh), fp32 acc. CTA 128x128, 8 warps, warp 64x32,
// K chunk 32, 2-stage cp.async pipeline, B via non-trans ldsm on B^T rows.
// blocks [0,1024): GEMM1 -> g_sim.  [1024,1536): GEMM2 -> expsum/diag (CL never stored:
//   logits bounded by 8 so unshifted sum-exp is safe; exp runs on MUFU, hidden under mma).
#define MMA_SMEM (8 * 5120 * 2)    // 81920 B
__global__ __launch_bounds__(256, 2) void k_mma(
    const __nv_bfloat16* __restrict__ pAh, const __nv_bfloat16* __restrict__ pAl,
    const __nv_bfloat16* __restrict__ pCTh, const __nv_bfloat16* __restrict__ pCTl,
    const __nv_bfloat16* __restrict__ pGTh, const __nv_bfloat16* __restrict__ pGTl,
    float* __restrict__ pSim) {
    extern __shared__ __align__(16) __nv_bfloat16 smem[];

    const __nv_bfloat16 *Ah, *Al, *Bh, *Bl;
    int bm, bn;
    int cta = blockIdx.x;
    if (cta < 1024) {
        bm = (cta >> 6) * 128; bn = (cta & 63) * 128;
        Ah = pAh; Al = pAl; Bh = pCTh; Bl = pCTl;
    } else {
        int t = cta - 1024;
        bm = (t >> 3) * 128; bn = (t & 7) * 128;
        Ah = pCTh; Al = pCTl; Bh = pGTh; Bl = pGTl;
    }

    int tid = threadIdx.x;
    int lane = tid & 31, w = tid >> 5;
    int wm = (w & 1) * 64, wn = (w >> 1) * 32;

    float acc[4][4][4];
#pragma unroll
    for (int i = 0; i < 4; i++)
#pragma unroll
        for (int j = 0; j < 4; j++)
#pragma unroll
            for (int q = 0; q < 4; q++) acc[i][j][q] = 0.f;

#define LOAD_STAGE(k0, s)                                                        \
    do {                                                                         \
        __nv_bfloat16* dAh = smem + (0 * 2 + (s)) * 5120;                        \
        __nv_bfloat16* dAl = smem + (1 * 2 + (s)) * 5120;                        \
        __nv_bfloat16* dBh = smem + (2 * 2 + (s)) * 5120;                        \
        __nv_bfloat16* dBl = smem + (3 * 2 + (s)) * 5120;                        \
        _Pragma("unroll")                                                        \
        for (int r = 0; r < 2; r++) {                                            \
            int idx = tid + r * 256;                                             \
            int row = idx >> 2, c4 = (idx & 3) * 8;                              \
            size_t ga = (size_t)(bm + row) * DIMK + (k0) + c4;                   \
            size_t gb = (size_t)(bn + row) * DIMK + (k0) + c4;                   \
            cpa16(sptr(dAh + row * 40 + c4), Ah + ga);                           \
            cpa16(sptr(dAl + row * 40 + c4), Al + ga);                           \
            cpa16(sptr(dBh + row * 40 + c4), Bh + gb);                           \
            cpa16(sptr(dBl + row * 40 + c4), Bl + gb);                           \
        }                                                                        \
    } while (0)

    LOAD_STAGE(0, 0);
    CPA_COMMIT();

    for (int c = 0; c < 16; c++) {
        int s = c & 1;
        if (c + 1 < 16) {
            LOAD_STAGE((c + 1) * 32, s ^ 1);
            CPA_COMMIT();
            CPA_WAIT(1);
        } else {
            CPA_WAIT(0);
        }
        __syncthreads();

        const __nv_bfloat16* sAh = smem + (0 * 2 + s) * 5120;
        const __nv_bfloat16* sAl = smem + (1 * 2 + s) * 5120;
        const __nv_bfloat16* sBh = smem + (2 * 2 + s) * 5120;
        const __nv_bfloat16* sBl = smem + (3 * 2 + s) * 5120;
#pragma unroll
        for (int kf = 0; kf < 32; kf += 16) {
            uint32_t ah[4][4], al[4][4], bh[4][2], bl[4][2], t[4];
            int aoff = (wm + (lane & 15)) * 40 + kf + (lane >> 4) * 8;
#pragma unroll
            for (int mt = 0; mt < 4; mt++) {
                ldsm_x4(ah[mt], sptr(sAh + aoff + mt * 16 * 40));
                ldsm_x4(al[mt], sptr(sAl + aoff + mt * 16 * 40));
            }
            int boff = (wn + (lane & 15)) * 40 + kf + (lane >> 4) * 8;
#pragma unroll
            for (int j = 0; j < 2; j++) {
                ldsm_x4(t, sptr(sBh + boff + j * 16 * 40));
                bh[2 * j][0] = t[0]; bh[2 * j][1] = t[2];
                bh[2 * j + 1][0] = t[1]; bh[2 * j + 1][1] = t[3];
                ldsm_x4(t, sptr(sBl + boff + j * 16 * 40));
                bl[2 * j][0] = t[0]; bl[2 * j][1] = t[2];
                bl[2 * j + 1][0] = t[1]; bl[2 * j + 1][1] = t[3];
            }
#pragma unroll
            for (int mt = 0; mt < 4; mt++)
#pragma unroll
                for (int nt = 0; nt < 4; nt++) {
                    mma_bf16(acc[mt][nt], ah[mt], bh[nt]);
                    mma_bf16(acc[mt][nt], ah[mt], bl[nt]);
                    mma_bf16(acc[mt][nt], al[mt], bh[nt]);
                }
        }
        __syncthreads();
    }

    int g = lane >> 2, t4 = (lane & 3) * 2;
    if (cta < 1024) {
        // GEMM1 epilogue: store sim tile
#pragma unroll
        for (int mt = 0; mt < 4; mt++)
#pragma unroll
            for (int nt = 0; nt < 4; nt++) {
                int r0 = bm + wm + mt * 16 + g;
                int cc = bn + wn + nt * 8 + t4;
                *(float2*)&pSim[(size_t)r0 * ALLNUM + cc] =
                    make_float2(acc[mt][nt][0], acc[mt][nt][1]);
                *(float2*)&pSim[(size_t)(r0 + 8) * ALLNUM + cc] =
                    make_float2(acc[mt][nt][2], acc[mt][nt][3]);
            }
    } else {
        // GEMM2 epilogue: unshifted sum-exp per row + diagonal logit, no CL store
#pragma unroll
        for (int mt = 0; mt < 4; mt++) {
            int r0 = bm + wm + mt * 16 + g;
            int r8 = r0 + 8;
            int d0 = r0 >> 3, d8 = r8 >> 3;
            float sA = 0.f, sB = 0.f;
#pragma unroll
            for (int nt = 0; nt < 4; nt++) {
                int cc = bn + wn + nt * 8 + t4;
                float v0 = acc[mt][nt][0], v1 = acc[mt][nt][1];
                float v2 = acc[mt][nt][2], v3 = acc[mt][nt][3];
                sA += __expf(v0) + __expf(v1);
                sB += __expf(v2) + __expf(v3);
                if (cc == d0) g_diag[r0] = v0;
                if (cc + 1 == d0) g_diag[r0] = v1;
                if (cc == d8) g_diag[r8] = v2;
                if (cc + 1 == d8) g_diag[r8] = v3;
            }
            sA += __shfl_xor_sync(0xffffffffu, sA, 1);
            sA += __shfl_xor_sync(0xffffffffu, sA, 2);
            sB += __shfl_xor_sync(0xffffffffu, sB, 1);
            sB += __shfl_xor_sync(0xffffffffu, sB, 2);
            if ((lane & 3) == 0) {
                atomicAdd(&g_sumexp[r0], sA);
                atomicAdd(&g_sumexp[r8], sB);
            }
        }
    }
#undef LOAD_STAGE
}

// ---------------- 5: per-row top-k threshold + masked-softmax classify loss ----------------
__global__ __launch_bounds__(256) void k_classify(const void* __restrict__ target,
                                                  const void* __restrict__ il) {
    __shared__ unsigned int uvals[ALLNUM];   // 32 KB
    __shared__ unsigned int hist[256];
    __shared__ float slog[C_CLASSES];        // 4 KB
    __shared__ float red[256];
    __shared__ unsigned int sh_prefix;
    __shared__ int sh_k;

    int tid = threadIdx.x;
    int lane = tid & 31;
    int b = blockIdx.x;
    int seq = g_il_seq;
    long long tgt = load_idx(target, b);
    const float* Srow = g_sim + (size_t)b * ALLNUM;

    if (seq) {
        for (int i = tid; i < ALLNUM; i += 256) {
            unsigned int bits = __float_as_uint(Srow[i]);
            uvals[i] = (bits & 0x80000000u) ? ~bits : (bits | 0x80000000u);
        }
    } else {
        for (int i = tid; i < ALLNUM; i += 256) {
            float v = Srow[i] + ((load_idx(il, i) == tgt) ? 1000.0f : 0.0f);
            unsigned int bits = __float_as_uint(v);
            uvals[i] = (bits & 0x80000000u) ? ~bits : (bits | 0x80000000u);
        }
    }
    for (int c = tid; c < C_CLASSES; c += 256) slog[c] = 0.f;
    if (tid == 0) { sh_prefix = 0u; sh_k = TOPK; }
    __syncthreads();
    if (seq && tid < 8) {           // patch the 8 boosted (target-class) entries
        int i = ((int)tgt << 3) + tid;
        unsigned int bits = __float_as_uint(Srow[i] + 1000.0f);
        uvals[i] = (bits & 0x80000000u) ? ~bits : (bits | 0x80000000u);
    }

    for (int shift = 24; shift >= 0; shift -= 8) {
        hist[tid] = 0u;
        __syncthreads();
        unsigned int pfx = sh_prefix;
        int k = sh_k;
        unsigned int hm = (shift == 24) ? 0u : (0xFFFFFFFFu << (shift + 8));
        for (int i = tid; i < ALLNUM; i += 256) {
            unsigned int u = uvals[i];
            int bin = ((u & hm) == pfx) ? (int)((u >> shift) & 255u) : -1;
            unsigned int m = __match_any_sync(0xffffffffu, bin);
            if (bin >= 0 && lane == (int)(__ffs(m) - 1))
                atomicAdd(&hist[bin], (unsigned int)__popc(m));
        }
        __syncthreads();
        if (tid == 0) {
            int cum = 0, d = 255;
            for (; d >= 0; d--) { cum += (int)hist[d]; if (cum >= k) break; }
            sh_k = k - (cum - (int)hist[d]);
            sh_prefix = pfx | ((unsigned int)d << shift);
        }
        __syncthreads();
    }
    unsigned int tau = sh_prefix;

    if (seq) {
        for (int i = tid; i < ALLNUM; i += 256) {
            if (uvals[i] >= tau) atomicAdd(&slog[i >> 3], Srow[i]);
        }
    } else {
        for (int i = tid; i < ALLNUM; i += 256) {
            if (uvals[i] >= tau) atomicAdd(&slog[(int)load_idx(il, i)], Srow[i]);
        }
    }
    __syncthreads();

    float part = 0.f;
    for (int c = tid; c < C_CLASSES; c += 256) {
        float l = slog[c];
        part += (l == 0.0f) ? 0.0f : __expf(l);
    }
    red[tid] = part;
    __syncthreads();
    for (int st = 128; st; st >>= 1) {
        if (tid < st) red[tid] += red[tid + st];
        __syncthreads();
    }
    if (tid == 0) {
        float S = red[0];
        float lt = slog[(int)tgt];
        float et = (lt == 0.0f) ? 0.0f : __expf(lt);
        float predict = et / (1e-8f + S);
        g_lossb[b] = -logf(predict + 1e-20f);
    }
}

// ---------------- 6: finalize regularizer rows: reg = log(sumexp) - diag ----------------
__global__ void k_regfin() {
    int i = blockIdx.x * 256 + threadIdx.x;
    g_regb[i] = logf(g_sumexp[i]) - g_diag[i];
}

// ---------------- 7: deterministic final reduction ----------------
__global__ void k_final(float* __restrict__ out, int out_size) {
    __shared__ float red[256];
    int tid = threadIdx.x;
    float s = 0.f;
    for (int i = tid; i < BATCH; i += 256) s += g_lossb[i];
    red[tid] = s;
    __syncthreads();
    for (int st = 128; st; st >>= 1) {
        if (tid < st) red[tid] += red[tid + st];
        __syncthreads();
    }
    float lc = red[0] / (float)BATCH;
    __syncthreads();
    s = 0.f;
    for (int i = tid; i < ALLNUM; i += 256) s += g_regb[i];
    red[tid] = s;
    __syncthreads();
    for (int st = 128; st; st >>= 1) {
        if (tid < st) red[tid] += red[tid + st];
        __syncthreads();
    }
    if (tid == 0) {
        float reg = red[0] / (float)ALLNUM;
        out[0] = lc + LAMB * reg;
        if (out_size > 1) out[1] = lc;
    }
}

// ---------------- launch ----------------
extern "C" void kernel_launch(void* const* d_in, const int* in_sizes, int n_in,
                              void* d_out, int out_size) {
    const float* input   = (const float*)d_in[0];
    const void*  target  = d_in[1];
    const float* proxies = (const float*)d_in[2];
    const void*  il      = d_in[3];
    float* out = (float*)d_out;

    static __nv_bfloat16 *pAh, *pAl, *pCTh, *pCTl, *pGTh, *pGTl;
    static float *pSim;
    static bool init = false;
    if (!init) {
        cudaGetSymbolAddress((void**)&pAh, gAh);
        cudaGetSymbolAddress((void**)&pAl, gAl);
        cudaGetSymbolAddress((void**)&pCTh, gCTh);
        cudaGetSymbolAddress((void**)&pCTl, gCTl);
        cudaGetSymbolAddress((void**)&pGTh, gGTh);
        cudaGetSymbolAddress((void**)&pGTl, gGTl);
        cudaGetSymbolAddress((void**)&pSim, g_sim);
        cudaFuncSetAttribute(k_mma, cudaFuncAttributeMaxDynamicSharedMemorySize,
                             MMA_SMEM);
        init = true;
    }

    dim3 gn(ALLNUM / 256, 8);
    k_norm2<<<gn, 256>>>(proxies, (const unsigned int*)target, il);   // #1
    k_fin_norm<<<ALLNUM / 256, 256>>>();                              // #2
    k_prep<<<5664, 256>>>(input, proxies, il);                        // #3

    // #4: fused GEMM1 (1024 CTAs) + GEMM2-with-reg-epilogue (512 CTAs) — profiled slot
    k_mma<<<1536, 256, MMA_SMEM>>>(pAh, pAl, pCTh, pCTl, pGTh, pGTl, pSim);

    k_classify<<<BATCH, 256>>>(target, il);                           // #5
    k_regfin<<<ALLNUM / 256, 256>>>();                                // #6
    k_final<<<1, 256>>>(out, out_size);                               // #7
}

// round 14
// speedup vs baseline: 1.1946x; 1.1630x over previous
#include <cuda_runtime.h>
#include <cuda_bf16.h>
#include <cstdint>
#include <math.h>

#define C_CLASSES 1024
#define ALLNUM    8192
#define DIMK      512
#define TOPK      410
#define BATCH     2048
#define LAMB      0.3f

// ---------------- scratch (static device globals: no allocation) ----------------
__device__ float g_invnorm[ALLNUM];
__device__ float g_norm2p[8][ALLNUM];
__device__ float g_sim[(size_t)BATCH * ALLNUM];            // 64 MB
__device__ float g_sumexp[ALLNUM];
__device__ float g_diag[ALLNUM];
__device__ float g_lossb[BATCH];
__device__ float g_regb[ALLNUM];
__device__ int   g_is64;
__device__ int   g_il_seq;

// bf16 hi/lo operands in TILED-SWIZZLED layout:
//   [row-tile][k-chunk][4096 elems], block = 128 rows x 32 cols (8 KB),
//   elem (rin,col) at rin*32 + ((col>>3) ^ ((rin>>1)&3))*8 + (col&7)
__device__ __nv_bfloat16 gAh[(size_t)BATCH * DIMK];        // 16 tiles
__device__ __nv_bfloat16 gAl[(size_t)BATCH * DIMK];
__device__ __nv_bfloat16 gCTh[(size_t)ALLNUM * DIMK];      // 64 tiles (scaled centers^T)
__device__ __nv_bfloat16 gCTl[(size_t)ALLNUM * DIMK];
__device__ __nv_bfloat16 gGTh[(size_t)C_CLASSES * DIMK];   // 8 tiles (G^T)
__device__ __nv_bfloat16 gGTl[(size_t)C_CLASSES * DIMK];

// ---------------- helpers ----------------
__device__ __forceinline__ long long load_idx(const void* p, int i) {
    if (g_is64) return ((const long long*)p)[i];
    return (long long)((const int*)p)[i];
}
__device__ __forceinline__ uint32_t sptr(const void* p) {
    return (uint32_t)__cvta_generic_to_shared(p);
}
// tiled-swizzled global index
__device__ __forceinline__ size_t tsw(int row, int k) {
    int g = ((k >> 3) & 3) ^ ((row >> 1) & 3);
    return ((size_t)(row >> 7) * 16 + (k >> 5)) * 4096
         + (row & 127) * 32 + (g << 3) + (k & 7);
}
__device__ __forceinline__ void mbar_init(uint32_t a, uint32_t cnt) {
    asm volatile("mbarrier.init.shared.b64 [%0], %1;" :: "r"(a), "r"(cnt) : "memory");
}
__device__ __forceinline__ void mbar_expect_tx(uint32_t a, uint32_t bytes) {
    asm volatile("mbarrier.arrive.expect_tx.shared.b64 _, [%0], %1;"
                 :: "r"(a), "r"(bytes) : "memory");
}
__device__ __forceinline__ void mbar_wait(uint32_t a, uint32_t parity) {
    uint32_t done = 0;
    while (!done) {
        asm volatile(
            "{\n\t.reg .pred p;\n\t"
            "mbarrier.try_wait.parity.acquire.cta.shared::cta.b64 p, [%1], %2, 0x989680;\n\t"
            "selp.b32 %0, 1, 0, p;\n\t}"
            : "=r"(done) : "r"(a), "r"(parity) : "memory");
    }
}
__device__ __forceinline__ void bulk_g2s(uint32_t dst, const void* src,
                                         uint32_t bytes, uint32_t mbar) {
    asm volatile(
        "cp.async.bulk.shared::cluster.global.mbarrier::complete_tx::bytes "
        "[%0], [%1], %2, [%3];"
        :: "r"(dst), "l"(src), "r"(bytes), "r"(mbar) : "memory");
}
__device__ __forceinline__ void ldsm_x4(uint32_t r[4], uint32_t addr) {
    asm volatile("ldmatrix.sync.aligned.m8n8.x4.shared.b16 {%0,%1,%2,%3}, [%4];"
                 : "=r"(r[0]), "=r"(r[1]), "=r"(r[2]), "=r"(r[3]) : "r"(addr));
}
__device__ __forceinline__ void mma_bf16(float d[4], const uint32_t a[4],
                                         const uint32_t b[2]) {
    asm volatile(
        "mma.sync.aligned.m16n8k16.row.col.f32.bf16.bf16.f32 "
        "{%0,%1,%2,%3}, {%4,%5,%6,%7}, {%8,%9}, {%0,%1,%2,%3};"
        : "+f"(d[0]), "+f"(d[1]), "+f"(d[2]), "+f"(d[3])
        : "r"(a[0]), "r"(a[1]), "r"(a[2]), "r"(a[3]), "r"(b[0]), "r"(b[1]));
}

// ---------------- 1: partial column norms + index/label-pattern detection ----------------
__global__ void k_norm2(const float* __restrict__ P, const unsigned int* __restrict__ t,
                        const void* __restrict__ il) {
    int a = blockIdx.x * 256 + threadIdx.x;
    int d0 = blockIdx.y * 64;
    float s0 = 0.f, s1 = 0.f, s2 = 0.f, s3 = 0.f;
#pragma unroll 4
    for (int d = 0; d < 64; d += 4) {
        float v0 = P[(size_t)(d0 + d + 0) * ALLNUM + a];
        float v1 = P[(size_t)(d0 + d + 1) * ALLNUM + a];
        float v2 = P[(size_t)(d0 + d + 2) * ALLNUM + a];
        float v3 = P[(size_t)(d0 + d + 3) * ALLNUM + a];
        s0 = fmaf(v0, v0, s0); s1 = fmaf(v1, v1, s1);
        s2 = fmaf(v2, v2, s2); s3 = fmaf(v3, v3, s3);
    }
    g_norm2p[blockIdx.y][a] = (s0 + s1) + (s2 + s3);

    if (blockIdx.x == 0 && blockIdx.y == 0) {
        __shared__ int s64, sok;
        if (threadIdx.x == 0) {
            int is64 = 1;
            for (int k = 0; k < 8; k++)
                if (t[2 * k + 1] != 0u) is64 = 0;
            g_is64 = is64; s64 = is64; sok = 1;
        }
        __syncthreads();
        int ok = 1;
        for (int i = threadIdx.x; i < ALLNUM; i += 256) {
            long long v = s64 ? ((const long long*)il)[i] : (long long)((const int*)il)[i];
            if (v != (long long)(i >> 3)) ok = 0;
        }
        if (!ok) atomicAnd(&sok, 0);
        __syncthreads();
        if (threadIdx.x == 0) g_il_seq = sok;
    }
}

// ---------------- 2: finalize inverse norms ----------------
__global__ void k_fin_norm() {
    int a = blockIdx.x * 256 + threadIdx.x;
    float s = 0.f;
#pragma unroll
    for (int j = 0; j < 8; j++) s += g_norm2p[j][a];
    g_invnorm[a] = 1.0f / fmaxf(sqrtf(s), 1e-12f);
}

// ---------------- 3: fused prep, writing the tiled-swizzled layouts ----------------
// flat grid: [0,4096) split_A, [4096,4608) groupsum->G^T, [4608,5632) split_PT, [5632,5664) zero
__global__ __launch_bounds__(256) void k_prep(const float* __restrict__ A,
                                              const float* __restrict__ P,
                                              const void* __restrict__ il) {
    int b = blockIdx.x, tid = threadIdx.x;
    if (b < 4096) {
        int i = b * 256 + tid;
        int row = i >> 9, k = i & 511;
        float x = A[i];
        __nv_bfloat16 h = __float2bfloat16(x);
        size_t o = tsw(row, k);
        gAh[o] = h;
        gAl[o] = __float2bfloat16(x - __bfloat162float(h));
    } else if (b < 4608) {
        int d = b - 4096;
        const float* Pd = P + (size_t)d * ALLNUM;
        if (g_il_seq) {
            for (int c = tid; c < C_CLASSES; c += 256) {
                const float4* p = (const float4*)(Pd + 8 * c);
                const float4* iv = (const float4*)(g_invnorm + 8 * c);
                float4 a0 = p[0], a1 = p[1], i0 = iv[0], i1 = iv[1];
                float s = a0.x * i0.x + a0.y * i0.y + a0.z * i0.z + a0.w * i0.w +
                          a1.x * i1.x + a1.y * i1.y + a1.z * i1.z + a1.w * i1.w;
                __nv_bfloat16 h = __float2bfloat16(s);
                size_t o = tsw(c, d);
                gGTh[o] = h;
                gGTl[o] = __float2bfloat16(s - __bfloat162float(h));
            }
        } else {
            __shared__ float g[C_CLASSES];
            for (int c = tid; c < C_CLASSES; c += 256) g[c] = 0.f;
            __syncthreads();
            for (int a = tid; a < ALLNUM; a += 256)
                atomicAdd(&g[(int)load_idx(il, a)], Pd[a] * g_invnorm[a]);
            __syncthreads();
            for (int c = tid; c < C_CLASSES; c += 256) {
                float s = g[c];
                __nv_bfloat16 h = __float2bfloat16(s);
                size_t o = tsw(c, d);
                gGTh[o] = h;
                gGTl[o] = __float2bfloat16(s - __bfloat162float(h));
            }
        }
    } else if (b < 5632) {
        __shared__ __nv_bfloat16 sh[64 * 66], sl[64 * 66];
        int t = b - 4608;
        int ab = (t & 127) * 64, kb = (t >> 7) * 64;
#pragma unroll
        for (int r = 0; r < 16; r++) {
            int idx = tid + r * 256;
            int kr = idx >> 6, ac = idx & 63;
            float v = P[(size_t)(kb + kr) * ALLNUM + ab + ac] * g_invnorm[ab + ac];
            __nv_bfloat16 h = __float2bfloat16(v);
            sh[kr * 66 + ac] = h;
            sl[kr * 66 + ac] = __float2bfloat16(v - __bfloat162float(h));
        }
        __syncthreads();
#pragma unroll
        for (int r = 0; r < 16; r++) {
            int idx = tid + r * 256;
            int ar = idx >> 6, kc = idx & 63;
            size_t o = tsw(ab + ar, kb + kc);
            gCTh[o] = sh[kc * 66 + ar];
            gCTl[o] = sl[kc * 66 + ar];
        }
    } else {
        int i = (b - 5632) * 256 + tid;
        g_sumexp[i] = 0.f;
    }
}

// ---------------- 4: fused tensor-core GEMMs, bulk-copy pipeline ----------------
// Operands tiled-swizzled. 3 passes (AhBh+AhBl+AlBh), fp32 acc.
// CTA 128x128, 8 warps (2x4), warp 64x32, K chunk 32, 2-stage, mbarrier-completed
// cp.async.bulk (4 x 8KB per chunk, single-thread issue; kills the LDGSTS issue floor).
// blocks [0,1024): GEMM1 -> g_sim.  [1024,1536): GEMM2 -> sumexp/diag epilogue.
#define STAGE_BYTES 32768
#define MMA_SMEM (2 * STAGE_BYTES + 1024)
__global__ __launch_bounds__(256, 2) void k_mma(
    const __nv_bfloat16* __restrict__ pAh, const __nv_bfloat16* __restrict__ pAl,
    const __nv_bfloat16* __restrict__ pCTh, const __nv_bfloat16* __restrict__ pCTl,
    const __nv_bfloat16* __restrict__ pGTh, const __nv_bfloat16* __restrict__ pGTl,
    float* __restrict__ pSim) {
    extern __shared__ __align__(1024) char smem[];
    uint32_t sb = sptr(smem);
    uint32_t mb0 = sb + 2 * STAGE_BYTES;      // two mbarriers at +0, +8

    const __nv_bfloat16 *Ah, *Al, *Bh, *Bl;
    int bm, bn;
    int cta = blockIdx.x;
    if (cta < 1024) {
        bm = (cta >> 6) * 128; bn = (cta & 63) * 128;
        Ah = pAh; Al = pAl; Bh = pCTh; Bl = pCTl;
    } else {
        int t = cta - 1024;
        bm = (t >> 3) * 128; bn = (t & 7) * 128;
        Ah = pCTh; Al = pCTl; Bh = pGTh; Bl = pGTl;
    }
    int aTile = bm >> 7, bTile = bn >> 7;

    int tid = threadIdx.x;
    int lane = tid & 31, w = tid >> 5;
    int wm = (w & 1) * 64, wn = (w >> 1) * 32;

    if (tid == 0) { mbar_init(mb0, 1); mbar_init(mb0 + 8, 1); }
    __syncthreads();
    asm volatile("fence.proxy.async.shared::cta;" ::: "memory");

    // issue chunk 0 -> stage 0, chunk 1 -> stage 1
    if (tid == 0) {
#pragma unroll
        for (int pc = 0; pc < 2; pc++) {
            uint32_t dst = sb + pc * STAGE_BYTES;
            uint32_t mb = mb0 + pc * 8;
            mbar_expect_tx(mb, STAGE_BYTES);
            bulk_g2s(dst,         Ah + ((size_t)aTile * 16 + pc) * 4096, 8192, mb);
            bulk_g2s(dst + 8192,  Al + ((size_t)aTile * 16 + pc) * 4096, 8192, mb);
            bulk_g2s(dst + 16384, Bh + ((size_t)bTile * 16 + pc) * 4096, 8192, mb);
            bulk_g2s(dst + 24576, Bl + ((size_t)bTile * 16 + pc) * 4096, 8192, mb);
        }
    }

    float acc[4][4][4];
#pragma unroll
    for (int i = 0; i < 4; i++)
#pragma unroll
        for (int j = 0; j < 4; j++)
#pragma unroll
            for (int q = 0; q < 4; q++) acc[i][j][q] = 0.f;

    for (int c = 0; c < 16; c++) {
        int s = c & 1;
        mbar_wait(mb0 + s * 8, (c >> 1) & 1);

        uint32_t sA = sb + s * STAGE_BYTES;           // Ah
        uint32_t sB = sA + 16384;                     // Bh
#pragma unroll
        for (int kf = 0; kf < 32; kf += 16) {
            uint32_t ah[4][4], al[4][4], bh[4][2], bl[4][2], t[4];
            int kg = (kf >> 3) + (lane >> 4);
#pragma unroll
            for (int mt = 0; mt < 4; mt++) {
                int arow = wm + (lane & 15) + mt * 16;
                int ag = kg ^ ((arow >> 1) & 3);
                uint32_t aaddr = sA + (arow * 32 + ag * 8) * 2;
                ldsm_x4(ah[mt], aaddr);
                ldsm_x4(al[mt], aaddr + 8192);
            }
#pragma unroll
            for (int j = 0; j < 2; j++) {
                int brow = wn + (lane & 15) + j * 16;
                int bg = kg ^ ((brow >> 1) & 3);
                uint32_t baddr = sB + (brow * 32 + bg * 8) * 2;
                // non-trans ldsm on B^T rows: r0=(n0-8,klo) r1=(n8-16,klo) r2/r3 = khi
                ldsm_x4(t, baddr);
                bh[2 * j][0] = t[0]; bh[2 * j][1] = t[2];
                bh[2 * j + 1][0] = t[1]; bh[2 * j + 1][1] = t[3];
                ldsm_x4(t, baddr + 8192);
                bl[2 * j][0] = t[0]; bl[2 * j][1] = t[2];
                bl[2 * j + 1][0] = t[1]; bl[2 * j + 1][1] = t[3];
            }
#pragma unroll
            for (int mt = 0; mt < 4; mt++)
#pragma unroll
                for (int nt = 0; nt < 4; nt++) {
                    mma_bf16(acc[mt][nt], ah[mt], bh[nt]);
                    mma_bf16(acc[mt][nt], ah[mt], bl[nt]);
                    mma_bf16(acc[mt][nt], al[mt], bh[nt]);
                }
        }
        __syncthreads();   // all warps done reading stage s
        if (tid == 0 && c + 2 < 16) {
            int nc = c + 2;
            uint32_t dst = sb + s * STAGE_BYTES;
            uint32_t mb = mb0 + s * 8;
            mbar_expect_tx(mb, STAGE_BYTES);
            bulk_g2s(dst,         Ah + ((size_t)aTile * 16 + nc) * 4096, 8192, mb);
            bulk_g2s(dst + 8192,  Al + ((size_t)aTile * 16 + nc) * 4096, 8192, mb);
            bulk_g2s(dst + 16384, Bh + ((size_t)bTile * 16 + nc) * 4096, 8192, mb);
            bulk_g2s(dst + 24576, Bl + ((size_t)bTile * 16 + nc) * 4096, 8192, mb);
        }
    }

    int g = lane >> 2, t4 = (lane & 3) * 2;
    if (cta < 1024) {
#pragma unroll
        for (int mt = 0; mt < 4; mt++)
#pragma unroll
            for (int nt = 0; nt < 4; nt++) {
                int r0 = bm + wm + mt * 16 + g;
                int cc = bn + wn + nt * 8 + t4;
                *(float2*)&pSim[(size_t)r0 * ALLNUM + cc] =
                    make_float2(acc[mt][nt][0], acc[mt][nt][1]);
                *(float2*)&pSim[(size_t)(r0 + 8) * ALLNUM + cc] =
                    make_float2(acc[mt][nt][2], acc[mt][nt][3]);
            }
    } else {
        // GEMM2 epilogue: unshifted sum-exp per row + diagonal logit (logits <= 8)
#pragma unroll
        for (int mt = 0; mt < 4; mt++) {
            int r0 = bm + wm + mt * 16 + g;
            int r8 = r0 + 8;
            int d0 = r0 >> 3, d8 = r8 >> 3;
            float sAc = 0.f, sBc = 0.f;
#pragma unroll
            for (int nt = 0; nt < 4; nt++) {
                int cc = bn + wn + nt * 8 + t4;
                float v0 = acc[mt][nt][0], v1 = acc[mt][nt][1];
                float v2 = acc[mt][nt][2], v3 = acc[mt][nt][3];
                sAc += __expf(v0) + __expf(v1);
                sBc += __expf(v2) + __expf(v3);
                if (cc == d0) g_diag[r0] = v0;
                if (cc + 1 == d0) g_diag[r0] = v1;
                if (cc == d8) g_diag[r8] = v2;
                if (cc + 1 == d8) g_diag[r8] = v3;
            }
            sAc += __shfl_xor_sync(0xffffffffu, sAc, 1);
            sAc += __shfl_xor_sync(0xffffffffu, sAc, 2);
            sBc += __shfl_xor_sync(0xffffffffu, sBc, 1);
            sBc += __shfl_xor_sync(0xffffffffu, sBc, 2);
            if ((lane & 3) == 0) {
                atomicAdd(&g_sumexp[r0], sAc);
                atomicAdd(&g_sumexp[r8], sBc);
            }
        }
    }
}

// ---------------- 5: per-row top-k threshold + masked-softmax classify loss ----------------
__global__ __launch_bounds__(256) void k_classify(const void* __restrict__ target,
                                                  const void* __restrict__ il) {
    __shared__ unsigned int uvals[ALLNUM];   // 32 KB
    __shared__ unsigned int hist[256];
    __shared__ float slog[C_CLASSES];        // 4 KB
    __shared__ float red[256];
    __shared__ unsigned int sh_prefix;
    __shared__ int sh_k;

    int tid = threadIdx.x;
    int lane = tid & 31;
    int b = blockIdx.x;
    int seq = g_il_seq;
    long long tgt = load_idx(target, b);
    const float* Srow = g_sim + (size_t)b * ALLNUM;

    if (seq) {
        for (int i = tid; i < ALLNUM; i += 256) {
            unsigned int bits = __float_as_uint(Srow[i]);
            uvals[i] = (bits & 0x80000000u) ? ~bits : (bits | 0x80000000u);
        }
    } else {
        for (int i = tid; i < ALLNUM; i += 256) {
            float v = Srow[i] + ((load_idx(il, i) == tgt) ? 1000.0f : 0.0f);
            unsigned int bits = __float_as_uint(v);
            uvals[i] = (bits & 0x80000000u) ? ~bits : (bits | 0x80000000u);
        }
    }
    for (int c = tid; c < C_CLASSES; c += 256) slog[c] = 0.f;
    if (tid == 0) { sh_prefix = 0u; sh_k = TOPK; }
    __syncthreads();
    if (seq && tid < 8) {
        int i = ((int)tgt << 3) + tid;
        unsigned int bits = __float_as_uint(Srow[i] + 1000.0f);
        uvals[i] = (bits & 0x80000000u) ? ~bits : (bits | 0x80000000u);
    }

    for (int shift = 24; shift >= 0; shift -= 8) {
        hist[tid] = 0u;
        __syncthreads();
        unsigned int pfx = sh_prefix;
        int k = sh_k;
        unsigned int hm = (shift == 24) ? 0u : (0xFFFFFFFFu << (shift + 8));
        for (int i = tid; i < ALLNUM; i += 256) {
            unsigned int u = uvals[i];
            int bin = ((u & hm) == pfx) ? (int)((u >> shift) & 255u) : -1;
            unsigned int m = __match_any_sync(0xffffffffu, bin);
            if (bin >= 0 && lane == (int)(__ffs(m) - 1))
                atomicAdd(&hist[bin], (unsigned int)__popc(m));
        }
        __syncthreads();
        if (tid == 0) {
            int cum = 0, d = 255;
            for (; d >= 0; d--) { cum += (int)hist[d]; if (cum >= k) break; }
            sh_k = k - (cum - (int)hist[d]);
            sh_prefix = pfx | ((unsigned int)d << shift);
        }
        __syncthreads();
    }
    unsigned int tau = sh_prefix;

    if (seq) {
        for (int i = tid; i < ALLNUM; i += 256) {
            if (uvals[i] >= tau) atomicAdd(&slog[i >> 3], Srow[i]);
        }
    } else {
        for (int i = tid; i < ALLNUM; i += 256) {
            if (uvals[i] >= tau) atomicAdd(&slog[(int)load_idx(il, i)], Srow[i]);
        }
    }
    __syncthreads();

    float part = 0.f;
    for (int c = tid; c < C_CLASSES; c += 256) {
        float l = slog[c];
        part += (l == 0.0f) ? 0.0f : __expf(l);
    }
    red[tid] = part;
    __syncthreads();
    for (int st = 128; st; st >>= 1) {
        if (tid < st) red[tid] += red[tid + st];
        __syncthreads();
    }
    if (tid == 0) {
        float S = red[0];
        float lt = slog[(int)tgt];
        float et = (lt == 0.0f) ? 0.0f : __expf(lt);
        float predict = et / (1e-8f + S);
        g_lossb[b] = -logf(predict + 1e-20f);
    }
}

// ---------------- 6: finalize regularizer rows ----------------
__global__ void k_regfin() {
    int i = blockIdx.x * 256 + threadIdx.x;
    g_regb[i] = logf(g_sumexp[i]) - g_diag[i];
}

// ---------------- 7: deterministic final reduction ----------------
__global__ void k_final(float* __restrict__ out, int out_size) {
    __shared__ float red[256];
    int tid = threadIdx.x;
    float s = 0.f;
    for (int i = tid; i < BATCH; i += 256) s += g_lossb[i];
    red[tid] = s;
    __syncthreads();
    for (int st = 128; st; st >>= 1) {
        if (tid < st) red[tid] += red[tid + st];
        __syncthreads();
    }
    float lc = red[0] / (float)BATCH;
    __syncthreads();
    s = 0.f;
    for (int i = tid; i < ALLNUM; i += 256) s += g_regb[i];
    red[tid] = s;
    __syncthreads();
    for (int st = 128; st; st >>= 1) {
        if (tid < st) red[tid] += red[tid + st];
        __syncthreads();
    }
    if (tid == 0) {
        float reg = red[0] / (float)ALLNUM;
        out[0] = lc + LAMB * reg;
        if (out_size > 1) out[1] = lc;
    }
}

// ---------------- launch ----------------
extern "C" void kernel_launch(void* const* d_in, const int* in_sizes, int n_in,
                              void* d_out, int out_size) {
    const float* input   = (const float*)d_in[0];
    const void*  target  = d_in[1];
    const float* proxies = (const float*)d_in[2];
    const void*  il      = d_in[3];
    float* out = (float*)d_out;

    static __nv_bfloat16 *pAh, *pAl, *pCTh, *pCTl, *pGTh, *pGTl;
    static float *pSim;
    static bool init = false;
    if (!init) {
        cudaGetSymbolAddress((void**)&pAh, gAh);
        cudaGetSymbolAddress((void**)&pAl, gAl);
        cudaGetSymbolAddress((void**)&pCTh, gCTh);
        cudaGetSymbolAddress((void**)&pCTl, gCTl);
        cudaGetSymbolAddress((void**)&pGTh, gGTh);
        cudaGetSymbolAddress((void**)&pGTl, gGTl);
        cudaGetSymbolAddress((void**)&pSim, g_sim);
        cudaFuncSetAttribute(k_mma, cudaFuncAttributeMaxDynamicSharedMemorySize,
                             MMA_SMEM);
        init = true;
    }

    dim3 gn(ALLNUM / 256, 8);
    k_norm2<<<gn, 256>>>(proxies, (const unsigned int*)target, il);   // #1
    k_fin_norm<<<ALLNUM / 256, 256>>>();                              // #2
    k_prep<<<5664, 256>>>(input, proxies, il);                        // #3

    // #4: fused GEMM1 + GEMM2 with bulk-copy pipeline — profiled slot
    k_mma<<<1536, 256, MMA_SMEM>>>(pAh, pAl, pCTh, pCTl, pGTh, pGTl, pSim);

    k_classify<<<BATCH, 256>>>(target, il);                           // #5
    k_regfin<<<ALLNUM / 256, 256>>>();                                // #6
    k_final<<<1, 256>>>(out, out_size);                               // #7
}

// round 15
// speedup vs baseline: 1.2201x; 1.0213x over previous
#include <cuda_runtime.h>
#include <cuda_bf16.h>
#include <cstdint>
#include <math.h>

#define C_CLASSES 1024
#define ALLNUM    8192
#define DIMK      512
#define TOPK      410
#define BATCH     2048
#define LAMB      0.3f

// ---------------- scratch (static device globals: no allocation) ----------------
__device__ float g_invnorm[ALLNUM];
__device__ float g_norm2p[8][ALLNUM];
__device__ float g_sim[(size_t)BATCH * ALLNUM];            // 64 MB
__device__ float g_sumexp[ALLNUM];
__device__ float g_diag[ALLNUM];
__device__ float g_lossb[BATCH];
__device__ float g_regb[ALLNUM];
__device__ int   g_is64;
__device__ int   g_il_seq;

// bf16 hi/lo operands in TILED-SWIZZLED layout:
//   [row-tile][k-chunk][4096 elems], block = 128 rows x 32 cols (8 KB),
//   elem (rin,col) at rin*32 + ((col>>3) ^ ((rin>>1)&3))*8 + (col&7)
__device__ __nv_bfloat16 gAh[(size_t)BATCH * DIMK];        // 16 tiles
__device__ __nv_bfloat16 gAl[(size_t)BATCH * DIMK];
__device__ __nv_bfloat16 gCTh[(size_t)ALLNUM * DIMK];      // 64 tiles (scaled centers^T)
__device__ __nv_bfloat16 gCTl[(size_t)ALLNUM * DIMK];
__device__ __nv_bfloat16 gGTh[(size_t)C_CLASSES * DIMK];   // 8 tiles (G^T)
__device__ __nv_bfloat16 gGTl[(size_t)C_CLASSES * DIMK];

// ---------------- helpers ----------------
__device__ __forceinline__ long long load_idx(const void* p, int i) {
    if (g_is64) return ((const long long*)p)[i];
    return (long long)((const int*)p)[i];
}
__device__ __forceinline__ uint32_t sptr(const void* p) {
    return (uint32_t)__cvta_generic_to_shared(p);
}
// tiled-swizzled global index
__device__ __forceinline__ size_t tsw(int row, int k) {
    int g = ((k >> 3) & 3) ^ ((row >> 1) & 3);
    return ((size_t)(row >> 7) * 16 + (k >> 5)) * 4096
         + (row & 127) * 32 + (g << 3) + (k & 7);
}
__device__ __forceinline__ void mbar_init(uint32_t a, uint32_t cnt) {
    asm volatile("mbarrier.init.shared.b64 [%0], %1;" :: "r"(a), "r"(cnt) : "memory");
}
__device__ __forceinline__ void mbar_expect_tx(uint32_t a, uint32_t bytes) {
    asm volatile("mbarrier.arrive.expect_tx.shared.b64 _, [%0], %1;"
                 :: "r"(a), "r"(bytes) : "memory");
}
__device__ __forceinline__ void mbar_arrive(uint32_t a) {
    asm volatile("mbarrier.arrive.shared.b64 _, [%0];" :: "r"(a) : "memory");
}
__device__ __forceinline__ void mbar_wait(uint32_t a, uint32_t parity) {
    uint32_t done = 0;
    while (!done) {
        asm volatile(
            "{\n\t.reg .pred p;\n\t"
            "mbarrier.try_wait.parity.acquire.cta.shared::cta.b64 p, [%1], %2, 0x989680;\n\t"
            "selp.b32 %0, 1, 0, p;\n\t}"
            : "=r"(done) : "r"(a), "r"(parity) : "memory");
    }
}
__device__ __forceinline__ void bulk_g2s(uint32_t dst, const void* src,
                                         uint32_t bytes, uint32_t mbar) {
    asm volatile(
        "cp.async.bulk.shared::cluster.global.mbarrier::complete_tx::bytes "
        "[%0], [%1], %2, [%3];"
        :: "r"(dst), "l"(src), "r"(bytes), "r"(mbar) : "memory");
}
__device__ __forceinline__ void ldsm_x4(uint32_t r[4], uint32_t addr) {
    asm volatile("ldmatrix.sync.aligned.m8n8.x4.shared.b16 {%0,%1,%2,%3}, [%4];"
                 : "=r"(r[0]), "=r"(r[1]), "=r"(r[2]), "=r"(r[3]) : "r"(addr));
}
__device__ __forceinline__ void mma_bf16(float d[4], const uint32_t a[4],
                                         const uint32_t b[2]) {
    asm volatile(
        "mma.sync.aligned.m16n8k16.row.col.f32.bf16.bf16.f32 "
        "{%0,%1,%2,%3}, {%4,%5,%6,%7}, {%8,%9}, {%0,%1,%2,%3};"
        : "+f"(d[0]), "+f"(d[1]), "+f"(d[2]), "+f"(d[3])
        : "r"(a[0]), "r"(a[1]), "r"(a[2]), "r"(a[3]), "r"(b[0]), "r"(b[1]));
}

// ---------------- 1: partial column norms + index/label-pattern detection ----------------
__global__ void k_norm2(const float* __restrict__ P, const unsigned int* __restrict__ t,
                        const void* __restrict__ il) {
    int a = blockIdx.x * 256 + threadIdx.x;
    int d0 = blockIdx.y * 64;
    float s0 = 0.f, s1 = 0.f, s2 = 0.f, s3 = 0.f;
#pragma unroll 4
    for (int d = 0; d < 64; d += 4) {
        float v0 = P[(size_t)(d0 + d + 0) * ALLNUM + a];
        float v1 = P[(size_t)(d0 + d + 1) * ALLNUM + a];
        float v2 = P[(size_t)(d0 + d + 2) * ALLNUM + a];
        float v3 = P[(size_t)(d0 + d + 3) * ALLNUM + a];
        s0 = fmaf(v0, v0, s0); s1 = fmaf(v1, v1, s1);
        s2 = fmaf(v2, v2, s2); s3 = fmaf(v3, v3, s3);
    }
    g_norm2p[blockIdx.y][a] = (s0 + s1) + (s2 + s3);

    if (blockIdx.x == 0 && blockIdx.y == 0) {
        __shared__ int s64, sok;
        if (threadIdx.x == 0) {
            int is64 = 1;
            for (int k = 0; k < 8; k++)
                if (t[2 * k + 1] != 0u) is64 = 0;
            g_is64 = is64; s64 = is64; sok = 1;
        }
        __syncthreads();
        int ok = 1;
        for (int i = threadIdx.x; i < ALLNUM; i += 256) {
            long long v = s64 ? ((const long long*)il)[i] : (long long)((const int*)il)[i];
            if (v != (long long)(i >> 3)) ok = 0;
        }
        if (!ok) atomicAnd(&sok, 0);
        __syncthreads();
        if (threadIdx.x == 0) g_il_seq = sok;
    }
}

// ---------------- 2: finalize inverse norms ----------------
__global__ void k_fin_norm() {
    int a = blockIdx.x * 256 + threadIdx.x;
    float s = 0.f;
#pragma unroll
    for (int j = 0; j < 8; j++) s += g_norm2p[j][a];
    g_invnorm[a] = 1.0f / fmaxf(sqrtf(s), 1e-12f);
}

// ---------------- 3: fused prep, writing the tiled-swizzled layouts ----------------
// flat grid: [0,4096) split_A, [4096,4608) groupsum->G^T, [4608,5632) split_PT, [5632,5664) zero
__global__ __launch_bounds__(256) void k_prep(const float* __restrict__ A,
                                              const float* __restrict__ P,
                                              const void* __restrict__ il) {
    int b = blockIdx.x, tid = threadIdx.x;
    if (b < 4096) {
        int i = b * 256 + tid;
        int row = i >> 9, k = i & 511;
        float x = A[i];
        __nv_bfloat16 h = __float2bfloat16(x);
        size_t o = tsw(row, k);
        gAh[o] = h;
        gAl[o] = __float2bfloat16(x - __bfloat162float(h));
    } else if (b < 4608) {
        int d = b - 4096;
        const float* Pd = P + (size_t)d * ALLNUM;
        if (g_il_seq) {
            for (int c = tid; c < C_CLASSES; c += 256) {
                const float4* p = (const float4*)(Pd + 8 * c);
                const float4* iv = (const float4*)(g_invnorm + 8 * c);
                float4 a0 = p[0], a1 = p[1], i0 = iv[0], i1 = iv[1];
                float s = a0.x * i0.x + a0.y * i0.y + a0.z * i0.z + a0.w * i0.w +
                          a1.x * i1.x + a1.y * i1.y + a1.z * i1.z + a1.w * i1.w;
                __nv_bfloat16 h = __float2bfloat16(s);
                size_t o = tsw(c, d);
                gGTh[o] = h;
                gGTl[o] = __float2bfloat16(s - __bfloat162float(h));
            }
        } else {
            __shared__ float g[C_CLASSES];
            for (int c = tid; c < C_CLASSES; c += 256) g[c] = 0.f;
            __syncthreads();
            for (int a = tid; a < ALLNUM; a += 256)
                atomicAdd(&g[(int)load_idx(il, a)], Pd[a] * g_invnorm[a]);
            __syncthreads();
            for (int c = tid; c < C_CLASSES; c += 256) {
                float s = g[c];
                __nv_bfloat16 h = __float2bfloat16(s);
                size_t o = tsw(c, d);
                gGTh[o] = h;
                gGTl[o] = __float2bfloat16(s - __bfloat162float(h));
            }
        }
    } else if (b < 5632) {
        __shared__ __nv_bfloat16 sh[64 * 66], sl[64 * 66];
        int t = b - 4608;
        int ab = (t & 127) * 64, kb = (t >> 7) * 64;
#pragma unroll
        for (int r = 0; r < 16; r++) {
            int idx = tid + r * 256;
            int kr = idx >> 6, ac = idx & 63;
            float v = P[(size_t)(kb + kr) * ALLNUM + ab + ac] * g_invnorm[ab + ac];
            __nv_bfloat16 h = __float2bfloat16(v);
            sh[kr * 66 + ac] = h;
            sl[kr * 66 + ac] = __float2bfloat16(v - __bfloat162float(h));
        }
        __syncthreads();
#pragma unroll
        for (int r = 0; r < 16; r++) {
            int idx = tid + r * 256;
            int ar = idx >> 6, kc = idx & 63;
            size_t o = tsw(ab + ar, kb + kc);
            gCTh[o] = sh[kc * 66 + ar];
            gCTl[o] = sl[kc * 66 + ar];
        }
    } else {
        int i = (b - 5632) * 256 + tid;
        g_sumexp[i] = 0.f;
    }
}

// ---------------- 4: fused tensor-core GEMMs, warp-decoupled bulk-copy pipeline ------------
// full[s]/empty[s] mbarrier pairs; per-chunk __syncthreads removed. Consumers wait full,
// each warp arrives empty after consuming; tid0 waits empty then issues chunk c+2.
// blocks [0,1024): GEMM1 -> g_sim.  [1024,1536): GEMM2 -> sumexp/diag epilogue.
#define STAGE_BYTES 32768
#define MMA_SMEM (2 * STAGE_BYTES + 1024)
__global__ __launch_bounds__(256, 2) void k_mma(
    const __nv_bfloat16* __restrict__ pAh, const __nv_bfloat16* __restrict__ pAl,
    const __nv_bfloat16* __restrict__ pCTh, const __nv_bfloat16* __restrict__ pCTl,
    const __nv_bfloat16* __restrict__ pGTh, const __nv_bfloat16* __restrict__ pGTl,
    float* __restrict__ pSim) {
    extern __shared__ __align__(1024) char smem[];
    uint32_t sb = sptr(smem);
    uint32_t mb0 = sb + 2 * STAGE_BYTES;   // full0 @+0, empty0 @+8, full1 @+16, empty1 @+24

    const __nv_bfloat16 *Ah, *Al, *Bh, *Bl;
    int bm, bn;
    int cta = blockIdx.x;
    if (cta < 1024) {
        bm = (cta >> 6) * 128; bn = (cta & 63) * 128;
        Ah = pAh; Al = pAl; Bh = pCTh; Bl = pCTl;
    } else {
        int t = cta - 1024;
        bm = (t >> 3) * 128; bn = (t & 7) * 128;
        Ah = pCTh; Al = pCTl; Bh = pGTh; Bl = pGTl;
    }
    int aTile = bm >> 7, bTile = bn >> 7;

    int tid = threadIdx.x;
    int lane = tid & 31, w = tid >> 5;
    int wm = (w & 1) * 64, wn = (w >> 1) * 32;

    if (tid == 0) {
        mbar_init(mb0 + 0, 1);  mbar_init(mb0 + 8, 8);     // full0 / empty0
        mbar_init(mb0 + 16, 1); mbar_init(mb0 + 24, 8);    // full1 / empty1
    }
    __syncthreads();
    asm volatile("fence.proxy.async.shared::cta;" ::: "memory");

    // issue chunk 0 -> stage 0, chunk 1 -> stage 1
    if (tid == 0) {
#pragma unroll
        for (int pc = 0; pc < 2; pc++) {
            uint32_t dst = sb + pc * STAGE_BYTES;
            uint32_t fb = mb0 + pc * 16;
            mbar_expect_tx(fb, STAGE_BYTES);
            bulk_g2s(dst,         Ah + ((size_t)aTile * 16 + pc) * 4096, 8192, fb);
            bulk_g2s(dst + 8192,  Al + ((size_t)aTile * 16 + pc) * 4096, 8192, fb);
            bulk_g2s(dst + 16384, Bh + ((size_t)bTile * 16 + pc) * 4096, 8192, fb);
            bulk_g2s(dst + 24576, Bl + ((size_t)bTile * 16 + pc) * 4096, 8192, fb);
        }
    }

    float acc[4][4][4];
#pragma unroll
    for (int i = 0; i < 4; i++)
#pragma unroll
        for (int j = 0; j < 4; j++)
#pragma unroll
            for (int q = 0; q < 4; q++) acc[i][j][q] = 0.f;

    for (int c = 0; c < 16; c++) {
        int s = c & 1;
        uint32_t fullb = mb0 + s * 16, emptyb = fullb + 8;
        uint32_t par = (c >> 1) & 1;
        mbar_wait(fullb, par);

        uint32_t sA = sb + s * STAGE_BYTES;           // Ah
        uint32_t sB = sA + 16384;                     // Bh
#pragma unroll
        for (int kf = 0; kf < 32; kf += 16) {
            uint32_t ah[4][4], al[4][4], bh[4][2], bl[4][2], t[4];
            int kg = (kf >> 3) + (lane >> 4);
#pragma unroll
            for (int mt = 0; mt < 4; mt++) {
                int arow = wm + (lane & 15) + mt * 16;
                int ag = kg ^ ((arow >> 1) & 3);
                uint32_t aaddr = sA + (arow * 32 + ag * 8) * 2;
                ldsm_x4(ah[mt], aaddr);
                ldsm_x4(al[mt], aaddr + 8192);
            }
#pragma unroll
            for (int j = 0; j < 2; j++) {
                int brow = wn + (lane & 15) + j * 16;
                int bg = kg ^ ((brow >> 1) & 3);
                uint32_t baddr = sB + (brow * 32 + bg * 8) * 2;
                // non-trans ldsm on B^T rows: r0=(n0-8,klo) r1=(n8-16,klo) r2/r3 = khi
                ldsm_x4(t, baddr);
                bh[2 * j][0] = t[0]; bh[2 * j][1] = t[2];
                bh[2 * j + 1][0] = t[1]; bh[2 * j + 1][1] = t[3];
                ldsm_x4(t, baddr + 8192);
                bl[2 * j][0] = t[0]; bl[2 * j][1] = t[2];
                bl[2 * j + 1][0] = t[1]; bl[2 * j + 1][1] = t[3];
            }
#pragma unroll
            for (int mt = 0; mt < 4; mt++)
#pragma unroll
                for (int nt = 0; nt < 4; nt++) {
                    mma_bf16(acc[mt][nt], ah[mt], bh[nt]);
                    mma_bf16(acc[mt][nt], ah[mt], bl[nt]);
                    mma_bf16(acc[mt][nt], al[mt], bh[nt]);
                }
        }
        // this warp is done with stage s
        if (lane == 0) mbar_arrive(emptyb);
        // producer: once all 8 warps consumed chunk c, refill stage s with chunk c+2
        if (tid == 0 && c + 2 < 16) {
            mbar_wait(emptyb, par);
            int nc = c + 2;
            uint32_t dst = sb + s * STAGE_BYTES;
            mbar_expect_tx(fullb, STAGE_BYTES);
            bulk_g2s(dst,         Ah + ((size_t)aTile * 16 + nc) * 4096, 8192, fullb);
            bulk_g2s(dst + 8192,  Al + ((size_t)aTile * 16 + nc) * 4096, 8192, fullb);
            bulk_g2s(dst + 16384, Bh + ((size_t)bTile * 16 + nc) * 4096, 8192, fullb);
            bulk_g2s(dst + 24576, Bl + ((size_t)bTile * 16 + nc) * 4096, 8192, fullb);
        }
    }

    int g = lane >> 2, t4 = (lane & 3) * 2;
    if (cta < 1024) {
#pragma unroll
        for (int mt = 0; mt < 4; mt++)
#pragma unroll
            for (int nt = 0; nt < 4; nt++) {
                int r0 = bm + wm + mt * 16 + g;
                int cc = bn + wn + nt * 8 + t4;
                *(float2*)&pSim[(size_t)r0 * ALLNUM + cc] =
                    make_float2(acc[mt][nt][0], acc[mt][nt][1]);
                *(float2*)&pSim[(size_t)(r0 + 8) * ALLNUM + cc] =
                    make_float2(acc[mt][nt][2], acc[mt][nt][3]);
            }
    } else {
        // GEMM2 epilogue: unshifted sum-exp per row + diagonal logit (logits <= 8)
#pragma unroll
        for (int mt = 0; mt < 4; mt++) {
            int r0 = bm + wm + mt * 16 + g;
            int r8 = r0 + 8;
            int d0 = r0 >> 3, d8 = r8 >> 3;
            float sAc = 0.f, sBc = 0.f;
#pragma unroll
            for (int nt = 0; nt < 4; nt++) {
                int cc = bn + wn + nt * 8 + t4;
                float v0 = acc[mt][nt][0], v1 = acc[mt][nt][1];
                float v2 = acc[mt][nt][2], v3 = acc[mt][nt][3];
                sAc += __expf(v0) + __expf(v1);
                sBc += __expf(v2) + __expf(v3);
                if (cc == d0) g_diag[r0] = v0;
                if (cc + 1 == d0) g_diag[r0] = v1;
                if (cc == d8) g_diag[r8] = v2;
                if (cc + 1 == d8) g_diag[r8] = v3;
            }
            sAc += __shfl_xor_sync(0xffffffffu, sAc, 1);
            sAc += __shfl_xor_sync(0xffffffffu, sAc, 2);
            sBc += __shfl_xor_sync(0xffffffffu, sBc, 1);
            sBc += __shfl_xor_sync(0xffffffffu, sBc, 2);
            if ((lane & 3) == 0) {
                atomicAdd(&g_sumexp[r0], sAc);
                atomicAdd(&g_sumexp[r8], sBc);
            }
        }
    }
}

// ---------------- 5: per-row top-k threshold + masked-softmax classify loss ----------------
// 512 threads/row; masked sum reconstructs sims from smem via the inverse bit map
// (bijective), so g_sim is read exactly once per row.
__global__ __launch_bounds__(512) void k_classify(const void* __restrict__ target,
                                                  const void* __restrict__ il) {
    __shared__ unsigned int uvals[ALLNUM];   // 32 KB
    __shared__ unsigned int hist[256];
    __shared__ float slog[C_CLASSES];        // 4 KB
    __shared__ float red[512];
    __shared__ unsigned int sh_prefix;
    __shared__ int sh_k;

    int tid = threadIdx.x;
    int lane = tid & 31;
    int b = blockIdx.x;
    int seq = g_il_seq;
    long long tgt = load_idx(target, b);
    const float* Srow = g_sim + (size_t)b * ALLNUM;

    if (seq) {
        for (int i = tid; i < ALLNUM; i += 512) {
            unsigned int bits = __float_as_uint(Srow[i]);
            uvals[i] = (bits & 0x80000000u) ? ~bits : (bits | 0x80000000u);
        }
    } else {
        for (int i = tid; i < ALLNUM; i += 512) {
            float v = Srow[i] + ((load_idx(il, i) == tgt) ? 1000.0f : 0.0f);
            unsigned int bits = __float_as_uint(v);
            uvals[i] = (bits & 0x80000000u) ? ~bits : (bits | 0x80000000u);
        }
    }
    for (int c = tid; c < C_CLASSES; c += 512) slog[c] = 0.f;
    if (tid == 0) { sh_prefix = 0u; sh_k = TOPK; }
    __syncthreads();
    if (seq && tid < 8) {           // patch the 8 boosted (target-class) entries
        int i = ((int)tgt << 3) + tid;
        unsigned int bits = __float_as_uint(Srow[i] + 1000.0f);
        uvals[i] = (bits & 0x80000000u) ? ~bits : (bits | 0x80000000u);
    }

    for (int shift = 24; shift >= 0; shift -= 8) {
        if (tid < 256) hist[tid] = 0u;
        __syncthreads();
        unsigned int pfx = sh_prefix;
        int k = sh_k;
        unsigned int hm = (shift == 24) ? 0u : (0xFFFFFFFFu << (shift + 8));
        for (int i = tid; i < ALLNUM; i += 512) {
            unsigned int u = uvals[i];
            int bin = ((u & hm) == pfx) ? (int)((u >> shift) & 255u) : -1;
            unsigned int m = __match_any_sync(0xffffffffu, bin);
            if (bin >= 0 && lane == (int)(__ffs(m) - 1))
                atomicAdd(&hist[bin], (unsigned int)__popc(m));
        }
        __syncthreads();
        if (tid == 0) {
            int cum = 0, d = 255;
            for (; d >= 0; d--) { cum += (int)hist[d]; if (cum >= k) break; }
            sh_k = k - (cum - (int)hist[d]);
            sh_prefix = pfx | ((unsigned int)d << shift);
        }
        __syncthreads();
    }
    unsigned int tau = sh_prefix;

    if (seq) {
        // non-target selected: invert bit map (exact). Target class: all 8 boosted
        // entries are selected by construction (boost >> any sim); add from gmem.
        int tg = (int)tgt;
        for (int i = tid; i < ALLNUM; i += 512) {
            unsigned int u = uvals[i];
            int cls = i >> 3;
            if (u >= tau && cls != tg) {
                unsigned int ob = (u & 0x80000000u) ? (u & 0x7FFFFFFFu) : ~u;
                atomicAdd(&slog[cls], __uint_as_float(ob));
            }
        }
        if (tid < 8) atomicAdd(&slog[tg], Srow[(tg << 3) + tid]);
    } else {
        for (int i = tid; i < ALLNUM; i += 512) {
            if (uvals[i] >= tau) atomicAdd(&slog[(int)load_idx(il, i)], Srow[i]);
        }
    }
    __syncthreads();

    float part = 0.f;
    for (int c = tid; c < C_CLASSES; c += 512) {
        float l = slog[c];
        part += (l == 0.0f) ? 0.0f : __expf(l);
    }
    red[tid] = part;
    __syncthreads();
    for (int st = 256; st; st >>= 1) {
        if (tid < st) red[tid] += red[tid + st];
        __syncthreads();
    }
    if (tid == 0) {
        float S = red[0];
        float lt = slog[(int)tgt];
        float et = (lt == 0.0f) ? 0.0f : __expf(lt);
        float predict = et / (1e-8f + S);
        g_lossb[b] = -logf(predict + 1e-20f);
    }
}

// ---------------- 6: finalize regularizer rows ----------------
__global__ void k_regfin() {
    int i = blockIdx.x * 256 + threadIdx.x;
    g_regb[i] = logf(g_sumexp[i]) - g_diag[i];
}

// ---------------- 7: deterministic final reduction ----------------
__global__ void k_final(float* __restrict__ out, int out_size) {
    __shared__ float red[256];
    int tid = threadIdx.x;
    float s = 0.f;
    for (int i = tid; i < BATCH; i += 256) s += g_lossb[i];
    red[tid] = s;
    __syncthreads();
    for (int st = 128; st; st >>= 1) {
        if (tid < st) red[tid] += red[tid + st];
        __syncthreads();
    }
    float lc = red[0] / (float)BATCH;
    __syncthreads();
    s = 0.f;
    for (int i = tid; i < ALLNUM; i += 256) s += g_regb[i];
    red[tid] = s;
    __syncthreads();
    for (int st = 128; st; st >>= 1) {
        if (tid < st) red[tid] += red[tid + st];
        __syncthreads();
    }
    if (tid == 0) {
        float reg = red[0] / (float)ALLNUM;
        out[0] = lc + LAMB * reg;
        if (out_size > 1) out[1] = lc;
    }
}

// ---------------- launch ----------------
extern "C" void kernel_launch(void* const* d_in, const int* in_sizes, int n_in,
                              void* d_out, int out_size) {
    const float* input   = (const float*)d_in[0];
    const void*  target  = d_in[1];
    const float* proxies = (const float*)d_in[2];
    const void*  il      = d_in[3];
    float* out = (float*)d_out;

    static __nv_bfloat16 *pAh, *pAl, *pCTh, *pCTl, *pGTh, *pGTl;
    static float *pSim;
    static bool init = false;
    if (!init) {
        cudaGetSymbolAddress((void**)&pAh, gAh);
        cudaGetSymbolAddress((void**)&pAl, gAl);
        cudaGetSymbolAddress((void**)&pCTh, gCTh);
        cudaGetSymbolAddress((void**)&pCTl, gCTl);
        cudaGetSymbolAddress((void**)&pGTh, gGTh);
        cudaGetSymbolAddress((void**)&pGTl, gGTl);
        cudaGetSymbolAddress((void**)&pSim, g_sim);
        cudaFuncSetAttribute(k_mma, cudaFuncAttributeMaxDynamicSharedMemorySize,
                             MMA_SMEM);
        init = true;
    }

    dim3 gn(ALLNUM / 256, 8);
    k_norm2<<<gn, 256>>>(proxies, (const unsigned int*)target, il);   // #1
    k_fin_norm<<<ALLNUM / 256, 256>>>();                              // #2
    k_prep<<<5664, 256>>>(input, proxies, il);                        // #3

    // #4: fused GEMMs, warp-decoupled pipeline — profiled slot
    k_mma<<<1536, 256, MMA_SMEM>>>(pAh, pAl, pCTh, pCTl, pGTh, pGTl, pSim);

    k_classify<<<BATCH, 512>>>(target, il);                           // #5
    k_regfin<<<ALLNUM / 256, 256>>>();                                // #6
    k_final<<<1, 256>>>(out, out_size);                               // #7
}